// round 14
// baseline (speedup 1.0000x reference)
#include <cuda_runtime.h>

#define DEG 32
#define D 128
#define NEG_SLOPE 0.01f

// Final champion: one node per CTA (HW rasterizer's dense block->address map,
// measured better than all software schedules), 4-warp cooperative reduction,
// evict-first streaming loads with 256B L2 prefetch hints, streaming store.
// Traffic = exactly compulsory 1.016 GB; DRAM duty ~90% = LTS path ceiling.
__device__ __forceinline__ float4 ldcs_pf256(const float4* p) {
    float4 v;
    asm("ld.global.cs.L2::256B.v4.f32 {%0,%1,%2,%3}, [%4];"
        : "=f"(v.x), "=f"(v.y), "=f"(v.z), "=f"(v.w)
        : "l"(p));
    return v;
}
__device__ __forceinline__ float ldcs_pf256_f(const float* p) {
    float v;
    asm("ld.global.cs.L2::256B.f32 %0, [%1];" : "=f"(v) : "l"(p));
    return v;
}

__global__ __launch_bounds__(128, 8)
void gat_reduce_kernel(const float* __restrict__ a1,
                       const float* __restrict__ a2,
                       const float* __restrict__ ft,
                       float* __restrict__ out)
{
    const int n    = blockIdx.x;
    const int tid  = threadIdx.x;        // 0..127
    const int warp = tid >> 5;           // 0..3
    const int lane = tid & 31;

    __shared__ float  s_g[DEG];          // per-neighbor logit sums
    __shared__ float  s_a1[4];           // a1 row-sum partials
    __shared__ float  s_e[DEG];          // softmax weights
    __shared__ float4 s_red[4][32];      // phase-2 cross-warp combine

    const size_t base = (size_t)n * DEG * D;
    const float4* a2v = reinterpret_cast<const float4*>(a2 + base);
    const float4* ftv = reinterpret_cast<const float4*>(ft + base);

    // ---- a1 row sum (128 threads, 1 float each), streaming load ----
    float v = ldcs_pf256_f(a1 + (size_t)n * D + tid);
    #pragma unroll
    for (int o = 16; o; o >>= 1) v += __shfl_down_sync(0xFFFFFFFFu, v, o);
    if (lane == 0) s_a1[warp] = v;

    // ---- per-neighbor sums: warp w handles g = w*8 .. w*8+7 ----
    float4 x[8];
    #pragma unroll
    for (int i = 0; i < 8; i++) {
        int g = warp * 8 + i;
        x[i] = ldcs_pf256(&a2v[g * (D / 4) + lane]);
    }
    #pragma unroll
    for (int i = 0; i < 8; i++) {
        float s = (x[i].x + x[i].y) + (x[i].z + x[i].w);
        #pragma unroll
        for (int o = 16; o; o >>= 1) s += __shfl_down_sync(0xFFFFFFFFu, s, o);
        if (lane == 0) s_g[warp * 8 + i] = s;
    }
    __syncthreads();

    // ---- softmax over 32 neighbors (warp 0) ----
    if (warp == 0) {
        float s1 = s_a1[0] + s_a1[1] + s_a1[2] + s_a1[3];
        float a  = s_g[lane] + s1;
        a = (a > 0.0f) ? a : NEG_SLOPE * a;               // leaky relu
        float m = a;
        #pragma unroll
        for (int o = 16; o; o >>= 1) m = fmaxf(m, __shfl_xor_sync(0xFFFFFFFFu, m, o));
        float e = __expf(a - m);
        float sum = e;
        #pragma unroll
        for (int o = 16; o; o >>= 1) sum += __shfl_xor_sync(0xFFFFFFFFu, sum, o);
        s_e[lane] = e / sum;
    }
    __syncthreads();

    // ---- weighted accumulation: warp handles g = warp, warp+4, ... ----
    float4 acc = make_float4(0.f, 0.f, 0.f, 0.f);
    #pragma unroll
    for (int i = 0; i < 8; i++) {
        int g = i * 4 + warp;
        float w = s_e[g];
        float4 f = ldcs_pf256(&ftv[g * (D / 4) + lane]);
        acc.x += w * f.x;
        acc.y += w * f.y;
        acc.z += w * f.z;
        acc.w += w * f.w;
    }
    s_red[warp][lane] = acc;
    __syncthreads();

    // ---- final 4-way combine + streaming store (warp 0) ----
    if (tid < 32) {
        float4 r0 = s_red[0][tid];
        float4 r1 = s_red[1][tid];
        float4 r2 = s_red[2][tid];
        float4 r3 = s_red[3][tid];
        float4 r;
        r.x = (r0.x + r1.x) + (r2.x + r3.x);
        r.y = (r0.y + r1.y) + (r2.y + r3.y);
        r.z = (r0.z + r1.z) + (r2.z + r3.z);
        r.w = (r0.w + r1.w) + (r2.w + r3.w);
        __stcs(&reinterpret_cast<float4*>(out + (size_t)n * D)[tid], r);
    }
}

extern "C" void kernel_launch(void* const* d_in, const int* in_sizes, int n_in,
                              void* d_out, int out_size)
{
    const float* a1 = (const float*)d_in[0];   // [N, D]
    const float* a2 = (const float*)d_in[1];   // [N, DEG, D]
    const float* ft = (const float*)d_in[2];   // [N, DEG, D]
    float* out = (float*)d_out;                // [N, D]

    int N = in_sizes[0] / D;
    gat_reduce_kernel<<<N, 128>>>(a1, a2, ft, out);
}